// round 1
// baseline (speedup 1.0000x reference)
#include <cuda_runtime.h>
#include <cuda_fp16.h>
#include <stdint.h>
#include <math.h>

#define MAXN 131072

// ---------------- device scratch (no allocations allowed) ----------------
__device__ __half g_hin [(size_t)MAXN * 32];    // padded MLP input  (N x 32)
__device__ __half g_actA[(size_t)MAXN * 512];   // activations ping
__device__ __half g_actB[(size_t)MAXN * 512];   // activations pong
__device__ float  g_cs  [(size_t)MAXN * 32];    // final-layer output (N x 32, 27 valid)
__device__ __half g_w0c [32 * 512];             // w0 padded to K=32
__device__ __half g_w1c [512 * 512];
__device__ __half g_w2c [512 * 512];
__device__ __half g_w3c [512 * 512];
__device__ __half g_wcc [512 * 32];             // wc padded to N=32
__device__ float  g_Kf  [121];                  // SH normalization K(l,m) (*sqrt2 for m>0), [l*11+m]

// ---------------- tables ----------------
__global__ void init_tables_kernel() {
    if (threadIdx.x == 0 && blockIdx.x == 0) {
        for (int l = 0; l <= 10; ++l) {
            for (int m = 0; m <= l; ++m) {
                double num = 1.0;                       // (l+m)!/(l-m)!
                for (int t = l - m + 1; t <= l + m; ++t) num *= (double)t;
                double K = sqrt((2.0 * l + 1.0) / (4.0 * 3.14159265358979323846) / num);
                g_Kf[l * 11 + m] = (float)((m > 0) ? (sqrt(2.0) * K) : K);
            }
        }
    }
}

// ---------------- weight conversion fp32 -> fp16 ----------------
__global__ void convert_weights_kernel(const float* __restrict__ w0, const float* __restrict__ w1,
                                       const float* __restrict__ w2, const float* __restrict__ w3,
                                       const float* __restrict__ wc) {
    int i = blockIdx.x * blockDim.x + threadIdx.x;
    if (i < 512 * 512) {
        g_w1c[i] = __float2half(w1[i]);
        g_w2c[i] = __float2half(w2[i]);
        g_w3c[i] = __float2half(w3[i]);
    }
    if (i < 32 * 512) {
        int k = i / 512;
        g_w0c[i] = (k < 8) ? __float2half(w0[i]) : __float2half(0.0f);
    }
    if (i < 512 * 32) {
        int k = i / 32, n = i % 32;
        g_wcc[i] = (n < 27) ? __float2half(wc[k * 27 + n]) : __float2half(0.0f);
    }
}

// ---------------- prep: SH (both dirs) fused with ref_SH dots ----------------
__global__ void __launch_bounds__(256) prep_kernel(
    const float* __restrict__ normals, const float* __restrict__ viewd,
    const float* __restrict__ feat, const float* __restrict__ refsh,
    float* out, int N)
{
    int i = blockIdx.x * blockDim.x + threadIdx.x;
    if (i >= N) return;

    float nx = normals[3 * i + 0], ny = normals[3 * i + 1], nz = normals[3 * i + 2];
    float vx = viewd[3 * i + 0],  vy = viewd[3 * i + 1],  vz = viewd[3 * i + 2];
    const float* f = feat + (size_t)i * 16;

    float fr = f[0];
    float rough = (fr > 0.0f) ? (fr + log1pf(expf(-fr))) : log1pf(expf(fr));   // softplus
    float dt = nx * vx + ny * vy + nz * vz;
    float wx = 2.0f * nx * dt - vx, wy = 2.0f * ny * dt - vy, wz = 2.0f * nz * dt - vz;

    // direction A = normal, direction B = reflected wr
    float rA = sqrtf(nx * nx + ny * ny + nz * nz);
    float iA = 1.0f / fmaxf(rA, 1e-12f);
    float xA = nx * iA, yA = ny * iA, zA = nz * iA;
    float rB = sqrtf(wx * wx + wy * wy + wz * wz);
    float iB = 1.0f / fmaxf(rB, 1e-12f);
    float xB = wx * iB, yB = wy * iB, zB = wz * iB;

    float cA[11], sA_[11], cB[11], sB_[11];
    cA[0] = 1.0f; sA_[0] = 0.0f; cB[0] = 1.0f; sB_[0] = 0.0f;
#pragma unroll
    for (int m = 1; m <= 10; ++m) {
        cA[m]  = xA * cA[m - 1] - yA * sA_[m - 1];
        sA_[m] = xA * sA_[m - 1] + yA * cA[m - 1];
        cB[m]  = xB * cB[m - 1] - yB * sB_[m - 1];
        sB_[m] = xB * sB_[m - 1] + yB * cB[m - 1];
    }

    const float LAM[11] = {3.1415926535897927f, 2.0943951023931957f, 0.7853981633974483f, 0.0f,
                           -0.13089969389957473f, 0.0f, 0.04908738521234052f, 0.0f,
                           -0.024543692606170262f, 0.0f, 0.014317154020265985f};
    const float DF[11] = {1.f, 1.f, 3.f, 15.f, 105.f, 945.f, 10395.f, 135135.f,
                          2027025.f, 34459425.f, 654729075.f};

    float q1A[11], q2A[11], q1B[11], q2B[11];
#pragma unroll
    for (int m = 0; m < 11; ++m) { q1A[m] = 0.f; q2A[m] = 0.f; q1B[m] = 0.f; q2B[m] = 0.f; }

    float ir0 = 0, ir1 = 0, ir2 = 0, lg0 = 0, lg1 = 0, lg2 = 0;
    float rlA = 1.0f, rlB = 1.0f;
    float e = expf(-rough), pw = 1.0f, decay = 1.0f;   // decay_l = e^{l(l+1)/2}
    const float* rp = refsh + (size_t)i * 363;

#pragma unroll
    for (int l = 0; l <= 10; ++l) {
        float qcA[11], qcB[11];
        if (l == 0) { qcA[0] = 1.0f; qcB[0] = 1.0f; }
        else {
            rlA *= rA; rlB *= rB; pw *= e; decay *= pw;
#pragma unroll
            for (int m = 0; m <= l - 2; ++m) {
                float inv = 1.0f / (float)(l - m);
                qcA[m] = ((float)(2 * l - 1) * zA * q1A[m] - (float)(l + m - 1) * q2A[m]) * inv;
                qcB[m] = ((float)(2 * l - 1) * zB * q1B[m] - (float)(l + m - 1) * q2B[m]) * inv;
            }
            qcA[l - 1] = (float)(2 * l - 1) * zA * q1A[l - 1];
            qcB[l - 1] = (float)(2 * l - 1) * zB * q1B[l - 1];
            qcA[l] = DF[l]; qcB[l] = DF[l];
        }
        int base = l * l + l;
        bool doIrr = (LAM[l] != 0.0f);
        {
            float kf = g_Kf[l * 11];
            float YA = kf * qcA[0] * rlA * LAM[l];
            float YB = kf * qcB[0] * rlB * decay;
            float r0 = rp[3 * base], r1 = rp[3 * base + 1], r2 = rp[3 * base + 2];
            if (doIrr) { ir0 += YA * r0; ir1 += YA * r1; ir2 += YA * r2; }
            lg0 += YB * r0; lg1 += YB * r1; lg2 += YB * r2;
        }
#pragma unroll
        for (int m = 1; m <= l; ++m) {
            float kf = g_Kf[l * 11 + m];
            float gA = kf * qcA[m] * rlA * LAM[l];
            float gB = kf * qcB[m] * rlB * decay;
            float p0 = rp[3 * (base + m)], p1 = rp[3 * (base + m) + 1], p2 = rp[3 * (base + m) + 2];
            float m0 = rp[3 * (base - m)], m1 = rp[3 * (base - m) + 1], m2 = rp[3 * (base - m) + 2];
            if (doIrr) {
                float ta = gA * cA[m], tb = gA * sA_[m];
                ir0 += ta * p0 + tb * m0; ir1 += ta * p1 + tb * m1; ir2 += ta * p2 + tb * m2;
            }
            float ua = gB * cB[m], ub = gB * sB_[m];
            lg0 += ua * p0 + ub * m0; lg1 += ua * p1 + ub * m1; lg2 += ua * p2 + ub * m2;
        }
#pragma unroll
        for (int m = 0; m <= l; ++m) {
            q2A[m] = q1A[m]; q1A[m] = qcA[m];
            q2B[m] = q1B[m]; q1B[m] = qcB[m];
        }
    }

    ir0 = fmaxf(ir0, 0.f); ir1 = fmaxf(ir1, 0.f); ir2 = fmaxf(ir2, 0.f);
    lg0 = fmaxf(lg0, 0.f); lg1 = fmaxf(lg1, 0.f); lg2 = fmaxf(lg2, 0.f);

    float a0 = 1.0f / (1.0f + expf(-f[10]));
    float a1 = 1.0f / (1.0f + expf(-f[11]));
    float a2 = 1.0f / (1.0f + expf(-f[12]));

    size_t N3 = (size_t)N * 3;
    // layout: raw[0,3N) albedo[3N,6N) diffuse[6N,9N) specular[9N,12N) sh_light[12N,18N)
    out[N3     + 3 * i + 0] = a0; out[N3     + 3 * i + 1] = a1; out[N3     + 3 * i + 2] = a2;
    out[2 * N3 + 3 * i + 0] = a0 * ir0; out[2 * N3 + 3 * i + 1] = a1 * ir1; out[2 * N3 + 3 * i + 2] = a2 * ir2;
    out[4 * N3 + 3 * i + 0] = lg0; out[4 * N3 + 3 * i + 1] = lg1; out[4 * N3 + 3 * i + 2] = lg2;
    out[5 * N3 + 3 * i + 0] = ir0; out[5 * N3 + 3 * i + 1] = ir1; out[5 * N3 + 3 * i + 2] = ir2;

    __half* hp = g_hin + (size_t)i * 32;
    hp[0] = __float2half(dt);
    hp[1] = __float2half(vx); hp[2] = __float2half(vy); hp[3] = __float2half(vz);
    hp[4] = __float2half(nx); hp[5] = __float2half(ny); hp[6] = __float2half(nz);
    hp[7] = __float2half(rough);
#pragma unroll
    for (int j = 8; j < 32; ++j) hp[j] = __float2half(0.0f);
}

// ---------------- fp16 tensor-core GEMM: C = act(A[M,K] @ B[K,Nout] + bias) ----------------
static __device__ __forceinline__ uint32_t smem_u32(const void* p) {
    return (uint32_t)__cvta_generic_to_shared(p);
}

__global__ void __launch_bounds__(256) gemm_kernel(
    const __half* __restrict__ A, const __half* __restrict__ B,
    const float* __restrict__ bias, __half* __restrict__ Ch, float* __restrict__ Cf,
    int M, int K, int ldB, int NoutReal, int doRelu)
{
    __shared__ __align__(16) __half sA[2][128][40];
    __shared__ __align__(16) __half sB[2][32][72];

    const int tid  = threadIdx.x;
    const int warp = tid >> 5, lane = tid & 31;
    const int wm = warp & 3, wn = warp >> 2;          // 4 warps along M, 2 along N
    const int m0 = blockIdx.x * 128;
    const int n0 = blockIdx.y * 64;

    float acc[2][4][4];
#pragma unroll
    for (int a = 0; a < 2; ++a)
#pragma unroll
        for (int b = 0; b < 4; ++b)
#pragma unroll
            for (int c = 0; c < 4; ++c) acc[a][b][c] = 0.0f;

    const int T = K / 32;

    auto issue_tile = [&](int t, int buf) {
        int k0 = t * 32;
        // A tile: 128x32 halves, 2 x 16B chunks per thread
#pragma unroll
        for (int c = 0; c < 2; ++c) {
            int ch = tid + c * 256;
            int r = ch >> 2, cc = (ch & 3) * 8;
            uint32_t dst = smem_u32(&sA[buf][r][cc]);
            if (m0 + r < M) {
                const __half* src = A + (size_t)(m0 + r) * K + k0 + cc;
                asm volatile("cp.async.cg.shared.global [%0], [%1], 16;\n" :: "r"(dst), "l"(src));
            } else {
                uint4 z = make_uint4(0, 0, 0, 0);
                *reinterpret_cast<uint4*>(&sA[buf][r][cc]) = z;
            }
        }
        // B tile: 32x64 halves, 1 x 16B chunk per thread
        {
            int r = tid >> 3, cc = (tid & 7) * 8;
            uint32_t dst = smem_u32(&sB[buf][r][cc]);
            if (n0 + cc < ldB) {
                const __half* src = B + (size_t)(k0 + r) * ldB + n0 + cc;
                asm volatile("cp.async.cg.shared.global [%0], [%1], 16;\n" :: "r"(dst), "l"(src));
            } else {
                uint4 z = make_uint4(0, 0, 0, 0);
                *reinterpret_cast<uint4*>(&sB[buf][r][cc]) = z;
            }
        }
    };

    issue_tile(0, 0);
    asm volatile("cp.async.commit_group;\n" ::: "memory");

    for (int t = 0; t < T; ++t) {
        int cur = t & 1;
        if (t + 1 < T) {
            issue_tile(t + 1, cur ^ 1);
            asm volatile("cp.async.commit_group;\n" ::: "memory");
            asm volatile("cp.async.wait_group 1;\n" ::: "memory");
        } else {
            asm volatile("cp.async.wait_group 0;\n" ::: "memory");
        }
        __syncthreads();

#pragma unroll
        for (int kk = 0; kk < 32; kk += 16) {
            uint32_t afr[2][4];
            uint32_t bfr[4][2];
#pragma unroll
            for (int mi = 0; mi < 2; ++mi) {
                uint32_t addr = smem_u32(&sA[cur][wm * 32 + mi * 16 + (lane & 15)][kk + (lane >> 4) * 8]);
                asm volatile("ldmatrix.sync.aligned.m8n8.x4.shared.b16 {%0,%1,%2,%3}, [%4];\n"
                             : "=r"(afr[mi][0]), "=r"(afr[mi][1]), "=r"(afr[mi][2]), "=r"(afr[mi][3])
                             : "r"(addr));
            }
#pragma unroll
            for (int ni = 0; ni < 4; ++ni) {
                uint32_t addr = smem_u32(&sB[cur][kk + (lane & 15)][wn * 32 + ni * 8]);
                asm volatile("ldmatrix.sync.aligned.m8n8.x2.trans.shared.b16 {%0,%1}, [%2];\n"
                             : "=r"(bfr[ni][0]), "=r"(bfr[ni][1]) : "r"(addr));
            }
#pragma unroll
            for (int mi = 0; mi < 2; ++mi)
#pragma unroll
                for (int ni = 0; ni < 4; ++ni) {
                    asm volatile(
                        "mma.sync.aligned.m16n8k16.row.col.f32.f16.f16.f32 "
                        "{%0,%1,%2,%3}, {%4,%5,%6,%7}, {%8,%9}, {%0,%1,%2,%3};\n"
                        : "+f"(acc[mi][ni][0]), "+f"(acc[mi][ni][1]),
                          "+f"(acc[mi][ni][2]), "+f"(acc[mi][ni][3])
                        : "r"(afr[mi][0]), "r"(afr[mi][1]), "r"(afr[mi][2]), "r"(afr[mi][3]),
                          "r"(bfr[ni][0]), "r"(bfr[ni][1]));
                }
        }
        __syncthreads();
    }

    // epilogue: bias + (relu) + store
#pragma unroll
    for (int mi = 0; mi < 2; ++mi) {
        int row0 = m0 + wm * 32 + mi * 16 + (lane >> 2);
#pragma unroll
        for (int ni = 0; ni < 4; ++ni) {
            int col = n0 + wn * 32 + ni * 8 + (lane & 3) * 2;
            float bv0 = (col < NoutReal) ? bias[col] : 0.0f;
            float bv1 = (col + 1 < NoutReal) ? bias[col + 1] : 0.0f;
#pragma unroll
            for (int rr = 0; rr < 2; ++rr) {
                int row = row0 + rr * 8;
                if (row >= M) continue;
                float v0 = acc[mi][ni][rr * 2 + 0] + bv0;
                float v1 = acc[mi][ni][rr * 2 + 1] + bv1;
                if (doRelu) { v0 = fmaxf(v0, 0.f); v1 = fmaxf(v1, 0.f); }
                if (Ch) {
                    __half2 hv = __floats2half2_rn(v0, v1);
                    *reinterpret_cast<__half2*>(Ch + (size_t)row * ldB + col) = hv;
                } else {
                    if (col     < NoutReal) Cf[(size_t)row * ldB + col]     = v0;
                    if (col + 1 < NoutReal) Cf[(size_t)row * ldB + col + 1] = v1;
                }
            }
        }
    }
}

// ---------------- final: gates + specular + raw_rgb ----------------
__global__ void __launch_bounds__(256) final_kernel(const float* __restrict__ feat, float* out, int N)
{
    int i = blockIdx.x * blockDim.x + threadIdx.x;
    if (i >= N) return;
    const float* cs = g_cs + (size_t)i * 32;
    const float* f = feat + (size_t)i * 16;
    float rr = 0.f, gg = 0.f, bb = 0.f;
#pragma unroll
    for (int j = 0; j < 9; ++j) {
        float cj = f[1 + j];
        rr += cs[j] * cj;
        gg += cs[9 + j] * cj;
        bb += cs[18 + j] * cj;
    }
    float gate0 = 1.0f / (1.0f + expf(-rr));
    float gate1 = 1.0f / (1.0f + expf(-gg));
    float gate2 = 1.0f / (1.0f + expf(-bb));
    float sp0 = 1.0f / (1.0f + expf(-f[13]));
    float sp1 = 1.0f / (1.0f + expf(-f[14]));
    float sp2 = 1.0f / (1.0f + expf(-f[15]));
    size_t N3 = (size_t)N * 3;
    float l0 = out[4 * N3 + 3 * i + 0], l1 = out[4 * N3 + 3 * i + 1], l2 = out[4 * N3 + 3 * i + 2];
    float d0 = out[2 * N3 + 3 * i + 0], d1 = out[2 * N3 + 3 * i + 1], d2 = out[2 * N3 + 3 * i + 2];
    float s0 = sp0 * l0 * gate0, s1 = sp1 * l1 * gate1, s2 = sp2 * l2 * gate2;
    out[3 * N3 + 3 * i + 0] = s0; out[3 * N3 + 3 * i + 1] = s1; out[3 * N3 + 3 * i + 2] = s2;
    out[3 * i + 0] = d0 + s0; out[3 * i + 1] = d1 + s1; out[3 * i + 2] = d2 + s2;
}

// ---------------- launch ----------------
extern "C" void kernel_launch(void* const* d_in, const int* in_sizes, int n_in,
                              void* d_out, int out_size)
{
    const float* normals = (const float*)d_in[0];
    const float* viewd   = (const float*)d_in[1];
    const float* feat    = (const float*)d_in[2];
    const float* refsh   = (const float*)d_in[3];
    const float* w0 = (const float*)d_in[4];  const float* b0 = (const float*)d_in[5];
    const float* w1 = (const float*)d_in[6];  const float* b1 = (const float*)d_in[7];
    const float* w2 = (const float*)d_in[8];  const float* b2 = (const float*)d_in[9];
    const float* w3 = (const float*)d_in[10]; const float* b3 = (const float*)d_in[11];
    const float* wc = (const float*)d_in[12]; const float* bc = (const float*)d_in[13];
    float* out = (float*)d_out;

    int N = in_sizes[0] / 3;
    if (N > MAXN) N = MAXN;

    void* p;
    cudaGetSymbolAddress(&p, g_hin);  __half* hin  = (__half*)p;
    cudaGetSymbolAddress(&p, g_actA); __half* actA = (__half*)p;
    cudaGetSymbolAddress(&p, g_actB); __half* actB = (__half*)p;
    cudaGetSymbolAddress(&p, g_cs);   float*  cs   = (float*)p;
    cudaGetSymbolAddress(&p, g_w0c);  __half* w0c  = (__half*)p;
    cudaGetSymbolAddress(&p, g_w1c);  __half* w1c  = (__half*)p;
    cudaGetSymbolAddress(&p, g_w2c);  __half* w2c  = (__half*)p;
    cudaGetSymbolAddress(&p, g_w3c);  __half* w3c  = (__half*)p;
    cudaGetSymbolAddress(&p, g_wcc);  __half* wcc  = (__half*)p;

    init_tables_kernel<<<1, 32>>>();
    convert_weights_kernel<<<(512 * 512 + 255) / 256, 256>>>(w0, w1, w2, w3, wc);
    prep_kernel<<<(N + 255) / 256, 256>>>(normals, viewd, feat, refsh, out, N);

    dim3 blk(256);
    dim3 g512((N + 127) / 128, 8);
    dim3 g32((N + 127) / 128, 1);
    gemm_kernel<<<g512, blk>>>(hin,  w0c, b0, actA, nullptr, N, 32,  512, 512, 1);
    gemm_kernel<<<g512, blk>>>(actA, w1c, b1, actB, nullptr, N, 512, 512, 512, 1);
    gemm_kernel<<<g512, blk>>>(actB, w2c, b2, actA, nullptr, N, 512, 512, 512, 1);
    gemm_kernel<<<g512, blk>>>(actA, w3c, b3, actB, nullptr, N, 512, 512, 512, 1);
    gemm_kernel<<<g32,  blk>>>(actB, wcc, bc, nullptr, cs,   N, 512, 32,  27,  0);

    final_kernel<<<(N + 255) / 256, 256>>>(feat, out, N);
}